// round 5
// baseline (speedup 1.0000x reference)
#include <cuda_runtime.h>
#include <mma.h>

using namespace nvcuda;

// Problem constants: TFRobertaSelfAttention B=2, S=2048, D=1024, H=16, HD=64
namespace {
constexpr int CB = 2;      // batch
constexpr int CS = 2048;   // seq len
constexpr int CD = 1024;   // hidden
constexpr int CH = 16;     // heads
constexpr int CHD = 64;    // head dim

// QKV GEMM tiling
constexpr int QKV_LDA = 40;    // 32 + 8 pad, 160B rows (16B-aligned, mult of 4 floats)
constexpr int QKV_LDB = 136;   // 128 + 8 pad, 544B rows
constexpr int QKV_LDC = 136;
constexpr int QKV_SMEM_BYTES = 128 * QKV_LDC * 4;  // 69632 (C phase is the max)

// Attention tiling
constexpr int ALD = 72;        // 64 + 8 pad, 288B rows (16B-aligned, mult of 4 floats)
constexpr int ATTN_SMEM_BYTES = (5 * 64 * ALD + 3 * 64) * 4;  // 92928
}

// Scratch for Q, K, V in [B, H, S, HD] layout (16 MB each). __device__ globals
// per the no-allocation rule.
__device__ __align__(16) float g_q[CB * CH * CS * CHD];
__device__ __align__(16) float g_k[CB * CH * CS * CHD];
__device__ __align__(16) float g_v[CB * CH * CS * CHD];

// ---------------------------------------------------------------------------
// Kernel 1: fused QKV projection.  Y = X @ W + b, scattered to [B,H,S,HD].
// blockIdx.z selects {Q, K, V}. Block tile 128x128, K-tile 32, TF32 WMMA.
// ---------------------------------------------------------------------------
__global__ __launch_bounds__(256, 2)
void qkv_kernel(const float* __restrict__ X,
                const float* __restrict__ Wq, const float* __restrict__ bq,
                const float* __restrict__ Wk, const float* __restrict__ bk,
                const float* __restrict__ Wv, const float* __restrict__ bv)
{
    extern __shared__ float sm[];
    float* As = sm;                      // 128 x QKV_LDA
    float* Bs = sm + 128 * QKV_LDA;      // 32  x QKV_LDB

    const int z = blockIdx.z;
    const float* W    = (z == 0) ? Wq : (z == 1) ? Wk : Wv;
    const float* bias = (z == 0) ? bq : (z == 1) ? bk : bv;
    float* Out        = (z == 0) ? g_q : (z == 1) ? g_k : g_v;

    const int m0 = blockIdx.y * 128;   // rows of X (B*S = 4096)
    const int n0 = blockIdx.x * 128;   // cols of W (D = 1024)
    const int tid  = threadIdx.x;
    const int warp = tid >> 5;
    const int wm = warp >> 2;          // 0..1 -> 64-row strip
    const int wn = warp & 3;           // 0..3 -> 32-col strip

    wmma::fragment<wmma::accumulator, 16, 16, 8, float> acc[4][2];
#pragma unroll
    for (int i = 0; i < 4; i++)
#pragma unroll
        for (int j = 0; j < 2; j++)
            wmma::fill_fragment(acc[i][j], 0.0f);

    for (int k0 = 0; k0 < CD; k0 += 32) {
        // Load A tile 128x32 (1024 float4s, 4 per thread)
#pragma unroll
        for (int it = 0; it < 4; it++) {
            int idx = tid + it * 256;
            int r = idx >> 3, c4 = idx & 7;
            *reinterpret_cast<float4*>(As + r * QKV_LDA + c4 * 4) =
                *reinterpret_cast<const float4*>(X + (m0 + r) * CD + k0 + c4 * 4);
        }
        // Load B tile 32x128
#pragma unroll
        for (int it = 0; it < 4; it++) {
            int idx = tid + it * 256;
            int r = idx >> 5, c4 = idx & 31;
            *reinterpret_cast<float4*>(Bs + r * QKV_LDB + c4 * 4) =
                *reinterpret_cast<const float4*>(W + (k0 + r) * CD + n0 + c4 * 4);
        }
        __syncthreads();

#pragma unroll
        for (int kk = 0; kk < 32; kk += 8) {
            wmma::fragment<wmma::matrix_a, 16, 16, 8, wmma::precision::tf32, wmma::row_major> af[4];
            wmma::fragment<wmma::matrix_b, 16, 16, 8, wmma::precision::tf32, wmma::row_major> bf[2];
#pragma unroll
            for (int i = 0; i < 4; i++) {
                wmma::load_matrix_sync(af[i], As + (wm * 64 + i * 16) * QKV_LDA + kk, QKV_LDA);
#pragma unroll
                for (int t = 0; t < af[i].num_elements; t++)
                    af[i].x[t] = wmma::__float_to_tf32(af[i].x[t]);
            }
#pragma unroll
            for (int j = 0; j < 2; j++) {
                wmma::load_matrix_sync(bf[j], Bs + kk * QKV_LDB + wn * 32 + j * 16, QKV_LDB);
#pragma unroll
                for (int t = 0; t < bf[j].num_elements; t++)
                    bf[j].x[t] = wmma::__float_to_tf32(bf[j].x[t]);
            }
#pragma unroll
            for (int i = 0; i < 4; i++)
#pragma unroll
                for (int j = 0; j < 2; j++)
                    wmma::mma_sync(acc[i][j], af[i], bf[j], acc[i][j]);
        }
        __syncthreads();
    }

    // Spill C tile to shared (reuse A/B space), then bias + head-split scatter.
    float* Cs = sm;
#pragma unroll
    for (int i = 0; i < 4; i++)
#pragma unroll
        for (int j = 0; j < 2; j++)
            wmma::store_matrix_sync(Cs + (wm * 64 + i * 16) * QKV_LDC + wn * 32 + j * 16,
                                    acc[i][j], QKV_LDC, wmma::mem_row_major);
    __syncthreads();

    for (int idx = tid; idx < 128 * 128; idx += 256) {
        int r = idx >> 7, cc = idx & 127;
        int grow = m0 + r;        // 0..4095 -> (b, s)
        int gcol = n0 + cc;       // 0..1023 -> (h, hd)
        int bb = grow >> 11;
        int s  = grow & (CS - 1);
        int h  = gcol >> 6;
        int hd = gcol & 63;
        Out[((bb * CH + h) * CS + s) * CHD + hd] = Cs[r * QKV_LDC + cc] + bias[gcol];
    }
}

// ---------------------------------------------------------------------------
// Kernel 2: flash attention.  One block = 64 queries of one (b, h).
// S tile = (Q*0.125) @ K^T via TF32 WMMA; online softmax; O += P @ V with
// accumulators round-tripped through a shared O tile (defined layouts only).
// ---------------------------------------------------------------------------
__global__ __launch_bounds__(256, 2)
void attn_kernel(const float* __restrict__ mask, float* __restrict__ out)
{
    extern __shared__ float sm[];
    float* Qs   = sm;                  // 64 x ALD (pre-scaled by 1/sqrt(HD))
    float* Ks   = Qs + 64 * ALD;
    float* Vs   = Ks + 64 * ALD;
    float* Ps   = Vs + 64 * ALD;       // scores, then probs
    float* Os   = Ps + 64 * ALD;       // running output accumulator
    float* rowm = Os + 64 * ALD;       // 64
    float* rowl = rowm + 64;           // 64
    float* ms   = rowl + 64;           // 64 (mask tile)

    const int q0 = blockIdx.x * 64;
    const int h  = blockIdx.y;
    const int b  = blockIdx.z;
    const int tid  = threadIdx.x;
    const int warp = tid >> 5;
    const int wm = warp >> 1;          // 0..3 -> 16-row strip
    const int wn = warp & 1;           // 0..1 -> 32-col strip

    const float* Qg = g_q + ((b * CH + h) * CS + q0) * CHD;
    const float* Kg = g_k + (b * CH + h) * CS * CHD;
    const float* Vg = g_v + (b * CH + h) * CS * CHD;

    const float scale = 0.125f;  // 1/sqrt(64)

    // Load Q tile (scaled), init O / m / l
    for (int idx = tid; idx < 64 * 16; idx += 256) {
        int r = idx >> 4, c4 = idx & 15;
        float4 v = *reinterpret_cast<const float4*>(Qg + r * CHD + c4 * 4);
        v.x *= scale; v.y *= scale; v.z *= scale; v.w *= scale;
        *reinterpret_cast<float4*>(Qs + r * ALD + c4 * 4) = v;
    }
    for (int idx = tid; idx < 64 * 64; idx += 256) {
        int r = idx >> 6, c = idx & 63;
        Os[r * ALD + c] = 0.0f;
    }
    if (tid < 64) { rowm[tid] = -1e30f; rowl[tid] = 0.0f; }
    __syncthreads();

    for (int kv = 0; kv < CS / 64; kv++) {
        // Load K and V tiles
        for (int idx = tid; idx < 64 * 16; idx += 256) {
            int r = idx >> 4, c4 = idx & 15;
            *reinterpret_cast<float4*>(Ks + r * ALD + c4 * 4) =
                *reinterpret_cast<const float4*>(Kg + (kv * 64 + r) * CHD + c4 * 4);
            *reinterpret_cast<float4*>(Vs + r * ALD + c4 * 4) =
                *reinterpret_cast<const float4*>(Vg + (kv * 64 + r) * CHD + c4 * 4);
        }
        if (tid < 64) ms[tid] = mask[b * CS + kv * 64 + tid];
        __syncthreads();

        // ---- S = Qs @ Ks^T ----
        wmma::fragment<wmma::accumulator, 16, 16, 8, float> cf[2];
        wmma::fill_fragment(cf[0], 0.0f);
        wmma::fill_fragment(cf[1], 0.0f);
#pragma unroll
        for (int kk = 0; kk < 64; kk += 8) {
            wmma::fragment<wmma::matrix_a, 16, 16, 8, wmma::precision::tf32, wmma::row_major> af;
            wmma::load_matrix_sync(af, Qs + (wm * 16) * ALD + kk, ALD);
#pragma unroll
            for (int t = 0; t < af.num_elements; t++)
                af.x[t] = wmma::__float_to_tf32(af.x[t]);
#pragma unroll
            for (int j = 0; j < 2; j++) {
                // B = K^T: element (k, n) = Ks[n][k] -> col-major with ld = ALD
                wmma::fragment<wmma::matrix_b, 16, 16, 8, wmma::precision::tf32, wmma::col_major> bf;
                wmma::load_matrix_sync(bf, Ks + (wn * 32 + j * 16) * ALD + kk, ALD);
#pragma unroll
                for (int t = 0; t < bf.num_elements; t++)
                    bf.x[t] = wmma::__float_to_tf32(bf.x[t]);
                wmma::mma_sync(cf[j], af, bf, cf[j]);
            }
        }
#pragma unroll
        for (int j = 0; j < 2; j++)
            wmma::store_matrix_sync(Ps + (wm * 16) * ALD + wn * 32 + j * 16,
                                    cf[j], ALD, wmma::mem_row_major);
        __syncthreads();

        // ---- online softmax: 4 threads per row, 16 cols each ----
        {
            int r = tid >> 2, sub = tid & 3;
            float* prow = Ps + r * ALD + sub * 16;
            float vals[16];
            float mloc = -1e30f;
#pragma unroll
            for (int i = 0; i < 16; i++) {
                vals[i] = prow[i] + ms[sub * 16 + i];
                mloc = fmaxf(mloc, vals[i]);
            }
            mloc = fmaxf(mloc, __shfl_xor_sync(0xffffffffu, mloc, 1));
            mloc = fmaxf(mloc, __shfl_xor_sync(0xffffffffu, mloc, 2));
            float mold = rowm[r];
            float mnew = fmaxf(mold, mloc);
            float corr = __expf(mold - mnew);
            float ssum = 0.0f;
#pragma unroll
            for (int i = 0; i < 16; i++) {
                float p = __expf(vals[i] - mnew);
                prow[i] = p;
                ssum += p;
            }
            ssum += __shfl_xor_sync(0xffffffffu, ssum, 1);
            ssum += __shfl_xor_sync(0xffffffffu, ssum, 2);
            // rescale running O rows
            float* orow = Os + r * ALD + sub * 16;
#pragma unroll
            for (int i = 0; i < 16; i++) orow[i] *= corr;
            if (sub == 0) { rowl[r] = rowl[r] * corr + ssum; rowm[r] = mnew; }
        }
        __syncthreads();

        // ---- O += P @ V ----
#pragma unroll
        for (int j = 0; j < 2; j++)
            wmma::load_matrix_sync(cf[j], Os + (wm * 16) * ALD + wn * 32 + j * 16,
                                   ALD, wmma::mem_row_major);
#pragma unroll
        for (int kk = 0; kk < 64; kk += 8) {
            wmma::fragment<wmma::matrix_a, 16, 16, 8, wmma::precision::tf32, wmma::row_major> af;
            wmma::load_matrix_sync(af, Ps + (wm * 16) * ALD + kk, ALD);
#pragma unroll
            for (int t = 0; t < af.num_elements; t++)
                af.x[t] = wmma::__float_to_tf32(af.x[t]);
#pragma unroll
            for (int j = 0; j < 2; j++) {
                wmma::fragment<wmma::matrix_b, 16, 16, 8, wmma::precision::tf32, wmma::row_major> bf;
                wmma::load_matrix_sync(bf, Vs + kk * ALD + wn * 32 + j * 16, ALD);
#pragma unroll
                for (int t = 0; t < bf.num_elements; t++)
                    bf.x[t] = wmma::__float_to_tf32(bf.x[t]);
                wmma::mma_sync(cf[j], af, bf, cf[j]);
            }
        }
#pragma unroll
        for (int j = 0; j < 2; j++)
            wmma::store_matrix_sync(Os + (wm * 16) * ALD + wn * 32 + j * 16,
                                    cf[j], ALD, wmma::mem_row_major);
        __syncthreads();
    }

    // Epilogue: out[b, s, h*64 + hd] = O / l   (merge-heads layout)
    for (int idx = tid; idx < 64 * 64; idx += 256) {
        int r = idx >> 6, c = idx & 63;
        out[(b * CS + q0 + r) * CD + h * CHD + c] = Os[r * ALD + c] / rowl[r];
    }
}

// ---------------------------------------------------------------------------
// kernel_launch
// Inputs (metadata order): hidden_states, attention_mask, Wq, bq, Wk, bk, Wv, bv
// ---------------------------------------------------------------------------
extern "C" void kernel_launch(void* const* d_in, const int* in_sizes, int n_in,
                              void* d_out, int out_size)
{
    (void)in_sizes; (void)n_in; (void)out_size;
    const float* X    = (const float*)d_in[0];
    const float* mask = (const float*)d_in[1];
    const float* Wq   = (const float*)d_in[2];
    const float* bq   = (const float*)d_in[3];
    const float* Wk   = (const float*)d_in[4];
    const float* bk   = (const float*)d_in[5];
    const float* Wv   = (const float*)d_in[6];
    const float* bv   = (const float*)d_in[7];
    float* out = (float*)d_out;

    cudaFuncSetAttribute(qkv_kernel, cudaFuncAttributeMaxDynamicSharedMemorySize,
                         QKV_SMEM_BYTES);
    cudaFuncSetAttribute(attn_kernel, cudaFuncAttributeMaxDynamicSharedMemorySize,
                         ATTN_SMEM_BYTES);

    // QKV: grid.x = N tiles (1024/128), grid.y = M tiles (4096/128), grid.z = {q,k,v}
    qkv_kernel<<<dim3(8, 32, 3), 256, QKV_SMEM_BYTES>>>(X, Wq, bq, Wk, bk, Wv, bv);
    // Attention: grid = (S/64 query tiles, H, B)
    attn_kernel<<<dim3(CS / 64, CH, CB), 256, ATTN_SMEM_BYTES>>>(mask, out);
}

// round 8
// speedup vs baseline: 1.8585x; 1.8585x over previous
#include <cuda_runtime.h>
#include <mma.h>

using namespace nvcuda;

// Problem constants: TFRobertaSelfAttention B=2, S=2048, D=1024, H=16, HD=64
namespace {
constexpr int CB = 2;      // batch
constexpr int CS = 2048;   // seq len
constexpr int CD = 1024;   // hidden
constexpr int CH = 16;     // heads
constexpr int CHD = 64;    // head dim

// QKV GEMM tiling
constexpr int QKV_LDA = 40;    // 32 + 8 pad
constexpr int QKV_LDB = 136;   // 128 + 8 pad
constexpr int QKV_LDC = 136;
constexpr int QKV_SMEM_BYTES = 128 * QKV_LDC * 4;  // 69632

// Attention tiling (raw mma version)
constexpr int LDK = 68;  // 68 % 32 == 4  -> S B-frag banks = g*4 + t  (all distinct)
constexpr int LDV = 72;  // 72 % 32 == 8  -> PV B-frag banks = t*8 + g (all distinct)
constexpr int KV_TILE = 64;
constexpr int NTILES = CS / KV_TILE;   // 32
}

// Scratch for Q, K, V in [B, H, S, HD] layout. __device__ globals per the
// no-allocation rule.
__device__ __align__(16) float g_q[CB * CH * CS * CHD];
__device__ __align__(16) float g_k[CB * CH * CS * CHD];
__device__ __align__(16) float g_v[CB * CH * CS * CHD];

// ---------------------------------------------------------------------------
// Kernel 1: fused QKV projection (unchanged from R4 passing version).
// ---------------------------------------------------------------------------
__global__ __launch_bounds__(256, 2)
void qkv_kernel(const float* __restrict__ X,
                const float* __restrict__ Wq, const float* __restrict__ bq,
                const float* __restrict__ Wk, const float* __restrict__ bk,
                const float* __restrict__ Wv, const float* __restrict__ bv)
{
    extern __shared__ float sm[];
    float* As = sm;                      // 128 x QKV_LDA
    float* Bs = sm + 128 * QKV_LDA;      // 32  x QKV_LDB

    const int z = blockIdx.z;
    const float* W    = (z == 0) ? Wq : (z == 1) ? Wk : Wv;
    const float* bias = (z == 0) ? bq : (z == 1) ? bk : bv;
    float* Out        = (z == 0) ? g_q : (z == 1) ? g_k : g_v;

    const int m0 = blockIdx.y * 128;
    const int n0 = blockIdx.x * 128;
    const int tid  = threadIdx.x;
    const int warp = tid >> 5;
    const int wm = warp >> 2;
    const int wn = warp & 3;

    wmma::fragment<wmma::accumulator, 16, 16, 8, float> acc[4][2];
#pragma unroll
    for (int i = 0; i < 4; i++)
#pragma unroll
        for (int j = 0; j < 2; j++)
            wmma::fill_fragment(acc[i][j], 0.0f);

    for (int k0 = 0; k0 < CD; k0 += 32) {
#pragma unroll
        for (int it = 0; it < 4; it++) {
            int idx = tid + it * 256;
            int r = idx >> 3, c4 = idx & 7;
            *reinterpret_cast<float4*>(As + r * QKV_LDA + c4 * 4) =
                *reinterpret_cast<const float4*>(X + (m0 + r) * CD + k0 + c4 * 4);
        }
#pragma unroll
        for (int it = 0; it < 4; it++) {
            int idx = tid + it * 256;
            int r = idx >> 5, c4 = idx & 31;
            *reinterpret_cast<float4*>(Bs + r * QKV_LDB + c4 * 4) =
                *reinterpret_cast<const float4*>(W + (k0 + r) * CD + n0 + c4 * 4);
        }
        __syncthreads();

#pragma unroll
        for (int kk = 0; kk < 32; kk += 8) {
            wmma::fragment<wmma::matrix_a, 16, 16, 8, wmma::precision::tf32, wmma::row_major> af[4];
            wmma::fragment<wmma::matrix_b, 16, 16, 8, wmma::precision::tf32, wmma::row_major> bf[2];
#pragma unroll
            for (int i = 0; i < 4; i++) {
                wmma::load_matrix_sync(af[i], As + (wm * 64 + i * 16) * QKV_LDA + kk, QKV_LDA);
#pragma unroll
                for (int t = 0; t < af[i].num_elements; t++)
                    af[i].x[t] = wmma::__float_to_tf32(af[i].x[t]);
            }
#pragma unroll
            for (int j = 0; j < 2; j++) {
                wmma::load_matrix_sync(bf[j], Bs + kk * QKV_LDB + wn * 32 + j * 16, QKV_LDB);
#pragma unroll
                for (int t = 0; t < bf[j].num_elements; t++)
                    bf[j].x[t] = wmma::__float_to_tf32(bf[j].x[t]);
            }
#pragma unroll
            for (int i = 0; i < 4; i++)
#pragma unroll
                for (int j = 0; j < 2; j++)
                    wmma::mma_sync(acc[i][j], af[i], bf[j], acc[i][j]);
        }
        __syncthreads();
    }

    float* Cs = sm;
#pragma unroll
    for (int i = 0; i < 4; i++)
#pragma unroll
        for (int j = 0; j < 2; j++)
            wmma::store_matrix_sync(Cs + (wm * 64 + i * 16) * QKV_LDC + wn * 32 + j * 16,
                                    acc[i][j], QKV_LDC, wmma::mem_row_major);
    __syncthreads();

    for (int idx = tid; idx < 128 * 128; idx += 256) {
        int r = idx >> 7, cc = idx & 127;
        int grow = m0 + r;
        int gcol = n0 + cc;
        int bb = grow >> 11;
        int s  = grow & (CS - 1);
        int h  = gcol >> 6;
        int hd = gcol & 63;
        Out[((bb * CH + h) * CS + s) * CHD + hd] = Cs[r * QKV_LDC + cc] + bias[gcol];
    }
}

// ---------------------------------------------------------------------------
// Raw tf32 mma m16n8k8.  Documented fragment layouts (g = lane>>2, t = lane&3):
//   A (16x8): a0=(g,t) a1=(g+8,t) a2=(g,t+4) a3=(g+8,t+4)
//   B (8x8, col-major as B[k][n]): b0=(t,g) b1=(t+4,g)
//   C (16x8): c0=(g,2t) c1=(g,2t+1) c2=(g+8,2t) c3=(g+8,2t+1)
// ---------------------------------------------------------------------------
__device__ __forceinline__ void mma_tf32(float* c, const unsigned* a,
                                         unsigned b0, unsigned b1)
{
    asm volatile(
        "mma.sync.aligned.m16n8k8.row.col.f32.tf32.tf32.f32 "
        "{%0,%1,%2,%3}, {%4,%5,%6,%7}, {%8,%9}, {%0,%1,%2,%3};"
        : "+f"(c[0]), "+f"(c[1]), "+f"(c[2]), "+f"(c[3])
        : "r"(a[0]), "r"(a[1]), "r"(a[2]), "r"(a[3]), "r"(b0), "r"(b1));
}

__device__ __forceinline__ unsigned f2tf32u(float x)
{
    return __float_as_uint(wmma::__float_to_tf32(x));
}

// ---------------------------------------------------------------------------
// Kernel 2: register-resident flash attention.
// Block = 128 queries of one (b,h); 8 warps, each owns 16 q-rows.
// Q frags + O accumulators + S/P stay in registers; only K/V go through smem.
// K/V tiles are register-prefetched one iteration ahead.
// ---------------------------------------------------------------------------
__global__ __launch_bounds__(256, 1)
void attn_kernel(const float* __restrict__ mask, float* __restrict__ out)
{
    __shared__ float Ks[KV_TILE * LDK];
    __shared__ float Vs[KV_TILE * LDV];
    __shared__ float ms[KV_TILE];

    const int q0 = blockIdx.x * 128;
    const int h  = blockIdx.y;
    const int b  = blockIdx.z;
    const int tid  = threadIdx.x;
    const int warp = tid >> 5;
    const int lane = tid & 31;
    const int g = lane >> 2;       // 0..7
    const int t = lane & 3;        // 0..3

    const float* Qg = g_q + ((b * CH + h) * CS + q0 + warp * 16) * CHD;
    const float* Kg = g_k + (b * CH + h) * CS * CHD;
    const float* Vg = g_v + (b * CH + h) * CS * CHD;
    const float* mg = mask + b * CS;

    // ---- Q fragments: loaded once, scaled by 1/sqrt(64), tf32-rounded ----
    unsigned qf[8][4];
#pragma unroll
    for (int kk = 0; kk < 8; kk++) {
#pragma unroll
        for (int e = 0; e < 4; e++) {
            int row = g + (e & 1) * 8;
            int col = kk * 8 + t + (e >> 1) * 4;
            qf[kk][e] = f2tf32u(Qg[row * CHD + col] * 0.125f);
        }
    }

    float oacc[8][4];
#pragma unroll
    for (int n = 0; n < 8; n++)
#pragma unroll
        for (int e = 0; e < 4; e++) oacc[n][e] = 0.0f;

    float m0 = -1e30f, m1 = -1e30f, l0 = 0.0f, l1 = 0.0f;

    // Prefetch registers for next K/V tile (+ mask slice)
    float4 kr[4], vr[4];
    float mreg = 0.0f;
    auto prefetch = [&](int j) {
#pragma unroll
        for (int i = 0; i < 4; i++) {
            int idx = tid + i * 256;          // 0..1023 float4s
            int r = idx >> 4, c4 = (idx & 15) * 4;
            kr[i] = *reinterpret_cast<const float4*>(Kg + (j * KV_TILE + r) * CHD + c4);
            vr[i] = *reinterpret_cast<const float4*>(Vg + (j * KV_TILE + r) * CHD + c4);
        }
        if (tid < KV_TILE) mreg = mg[j * KV_TILE + tid];
    };

    prefetch(0);

    for (int j = 0; j < NTILES; j++) {
        // ---- commit prefetched tile to shared (tf32-rounded) ----
#pragma unroll
        for (int i = 0; i < 4; i++) {
            int idx = tid + i * 256;
            int r = idx >> 4, c4 = (idx & 15) * 4;
            float4 kq, vq;
            kq.x = wmma::__float_to_tf32(kr[i].x); kq.y = wmma::__float_to_tf32(kr[i].y);
            kq.z = wmma::__float_to_tf32(kr[i].z); kq.w = wmma::__float_to_tf32(kr[i].w);
            vq.x = wmma::__float_to_tf32(vr[i].x); vq.y = wmma::__float_to_tf32(vr[i].y);
            vq.z = wmma::__float_to_tf32(vr[i].z); vq.w = wmma::__float_to_tf32(vr[i].w);
            *reinterpret_cast<float4*>(Ks + r * LDK + c4) = kq;
            *reinterpret_cast<float4*>(Vs + r * LDV + c4) = vq;
        }
        if (tid < KV_TILE) ms[tid] = mreg;
        __syncthreads();

        if (j + 1 < NTILES) prefetch(j + 1);  // LDGs overlap with compute below

        // ---- S = (Q/8) @ K^T : 8 N-tiles of 16x8, k = 64 ----
        float s[8][4];
#pragma unroll
        for (int n = 0; n < 8; n++)
#pragma unroll
            for (int e = 0; e < 4; e++) s[n][e] = 0.0f;

#pragma unroll
        for (int kk = 0; kk < 8; kk++) {
#pragma unroll
            for (int n = 0; n < 8; n++) {
                // B[k][n] = K^T[kk*8+t][n*8+g] = Ks[n*8+g][kk*8+t]
                unsigned b0 = __float_as_uint(Ks[(n * 8 + g) * LDK + kk * 8 + t]);
                unsigned b1 = __float_as_uint(Ks[(n * 8 + g) * LDK + kk * 8 + t + 4]);
                mma_tf32(s[n], qf[kk], b0, b1);
            }
        }

        // ---- online softmax on register-resident S ----
        float mgx = -1e30f, mhx = -1e30f;
#pragma unroll
        for (int n = 0; n < 8; n++) {
            float2 mk = *reinterpret_cast<const float2*>(&ms[n * 8 + t * 2]);
            s[n][0] += mk.x; s[n][1] += mk.y;
            s[n][2] += mk.x; s[n][3] += mk.y;
            mgx = fmaxf(mgx, fmaxf(s[n][0], s[n][1]));
            mhx = fmaxf(mhx, fmaxf(s[n][2], s[n][3]));
        }
        mgx = fmaxf(mgx, __shfl_xor_sync(0xffffffffu, mgx, 1));
        mgx = fmaxf(mgx, __shfl_xor_sync(0xffffffffu, mgx, 2));
        mhx = fmaxf(mhx, __shfl_xor_sync(0xffffffffu, mhx, 1));
        mhx = fmaxf(mhx, __shfl_xor_sync(0xffffffffu, mhx, 2));

        float mn0 = fmaxf(m0, mgx), mn1 = fmaxf(m1, mhx);
        float c0 = __expf(m0 - mn0), c1 = __expf(m1 - mn1);
        m0 = mn0; m1 = mn1;

        float s0 = 0.0f, s1 = 0.0f;
#pragma unroll
        for (int n = 0; n < 8; n++) {
            s[n][0] = __expf(s[n][0] - mn0); s0 += s[n][0];
            s[n][1] = __expf(s[n][1] - mn0); s0 += s[n][1];
            s[n][2] = __expf(s[n][2] - mn1); s1 += s[n][2];
            s[n][3] = __expf(s[n][3] - mn1); s1 += s[n][3];
        }
        s0 += __shfl_xor_sync(0xffffffffu, s0, 1);
        s0 += __shfl_xor_sync(0xffffffffu, s0, 2);
        s1 += __shfl_xor_sync(0xffffffffu, s1, 1);
        s1 += __shfl_xor_sync(0xffffffffu, s1, 2);
        l0 = l0 * c0 + s0;
        l1 = l1 * c1 + s1;

#pragma unroll
        for (int n = 0; n < 8; n++) {
            oacc[n][0] *= c0; oacc[n][1] *= c0;
            oacc[n][2] *= c1; oacc[n][3] *= c1;
        }

        // ---- O += P @ V ----
        const int srcA = (lane & ~3) | (t >> 1);   // holds cols 2*(t>>1), +1  -> col t
        const int srcB = srcA + 2;                 // -> col t+4
        const bool odd = (t & 1);
#pragma unroll
        for (int kk = 0; kk < 8; kk++) {
            // Redistribute P tile kk from accumulator layout (cols 2t,2t+1)
            // to A-operand layout (cols t, t+4) via intra-quad shuffles.
            float e0 = __shfl_sync(0xffffffffu, s[kk][0], srcA);
            float o0 = __shfl_sync(0xffffffffu, s[kk][1], srcA);
            float e1 = __shfl_sync(0xffffffffu, s[kk][2], srcA);
            float o1 = __shfl_sync(0xffffffffu, s[kk][3], srcA);
            float e2 = __shfl_sync(0xffffffffu, s[kk][0], srcB);
            float o2 = __shfl_sync(0xffffffffu, s[kk][1], srcB);
            float e3 = __shfl_sync(0xffffffffu, s[kk][2], srcB);
            float o3 = __shfl_sync(0xffffffffu, s[kk][3], srcB);
            unsigned a[4];
            a[0] = f2tf32u(odd ? o0 : e0);   // P(g,    kk*8 + t)
            a[1] = f2tf32u(odd ? o1 : e1);   // P(g+8,  kk*8 + t)
            a[2] = f2tf32u(odd ? o2 : e2);   // P(g,    kk*8 + t+4)
            a[3] = f2tf32u(odd ? o3 : e3);   // P(g+8,  kk*8 + t+4)
#pragma unroll
            for (int n = 0; n < 8; n++) {
                // B[k][n] = V[kk*8+t][n*8+g]
                unsigned b0 = __float_as_uint(Vs[(kk * 8 + t) * LDV + n * 8 + g]);
                unsigned b1 = __float_as_uint(Vs[(kk * 8 + t + 4) * LDV + n * 8 + g]);
                mma_tf32(oacc[n], a, b0, b1);
            }
        }
        __syncthreads();
    }

    // ---- epilogue: out[b, s, h*64 + c] = O / l ----
    const float r0 = 1.0f / l0, r1 = 1.0f / l1;
    const int row_g = q0 + warp * 16 + g;
#pragma unroll
    for (int n = 0; n < 8; n++) {
        float2 v0 = make_float2(oacc[n][0] * r0, oacc[n][1] * r0);
        float2 v1 = make_float2(oacc[n][2] * r1, oacc[n][3] * r1);
        *reinterpret_cast<float2*>(out + (size_t)(b * CS + row_g) * CD + h * CHD + n * 8 + t * 2) = v0;
        *reinterpret_cast<float2*>(out + (size_t)(b * CS + row_g + 8) * CD + h * CHD + n * 8 + t * 2) = v1;
    }
}

// ---------------------------------------------------------------------------
// kernel_launch
// Inputs (metadata order): hidden_states, attention_mask, Wq, bq, Wk, bk, Wv, bv
// ---------------------------------------------------------------------------
extern "C" void kernel_launch(void* const* d_in, const int* in_sizes, int n_in,
                              void* d_out, int out_size)
{
    (void)in_sizes; (void)n_in; (void)out_size;
    const float* X    = (const float*)d_in[0];
    const float* mask = (const float*)d_in[1];
    const float* Wq   = (const float*)d_in[2];
    const float* bq   = (const float*)d_in[3];
    const float* Wk   = (const float*)d_in[4];
    const float* bk   = (const float*)d_in[5];
    const float* Wv   = (const float*)d_in[6];
    const float* bv   = (const float*)d_in[7];
    float* out = (float*)d_out;

    cudaFuncSetAttribute(qkv_kernel, cudaFuncAttributeMaxDynamicSharedMemorySize,
                         QKV_SMEM_BYTES);

    // QKV: grid.x = N tiles (1024/128), grid.y = M tiles (4096/128), grid.z = {q,k,v}
    qkv_kernel<<<dim3(8, 32, 3), 256, QKV_SMEM_BYTES>>>(X, Wq, bq, Wk, bk, Wv, bv);
    // Attention: grid = (S/128 query tiles, H, B)
    attn_kernel<<<dim3(CS / 128, CH, CB), 256>>>(mask, out);
}

// round 13
// speedup vs baseline: 2.8930x; 1.5567x over previous
#include <cuda_runtime.h>
#include <mma.h>

using namespace nvcuda;

// Problem constants: TFRobertaSelfAttention B=2, S=2048, D=1024, H=16, HD=64
namespace {
constexpr int CB = 2;      // batch
constexpr int CS = 2048;   // seq len
constexpr int CD = 1024;   // hidden
constexpr int CH = 16;     // heads
constexpr int CHD = 64;    // head dim

// QKV tiling: block 256(M) x 128(N), K-step 16, 8 warps of 64x64
constexpr int QLDA = 20;     // 16 + 4 pad: banks g*20+t all distinct mod 32
constexpr int QLDB = 136;    // 128 + 8 pad: banks t*8+g distinct
constexpr int QABUF = 256 * QLDA;   // 5120 floats per buffer
constexpr int QBBUF = 16 * QLDB;    // 2176 floats per buffer
constexpr int QKV_SMEM = (2 * QABUF + 2 * QBBUF) * 4;  // 58368 B

// Attention tiling: block = 128 q rows, 4 warps x 32 rows, KV tile 64
constexpr int LDK = 68;      // banks g*4+t distinct
constexpr int LDV = 72;      // banks t*8+g distinct
constexpr int KBUF = 64 * LDK;   // 4352
constexpr int VBUF = 64 * LDV;   // 4608
constexpr int NTILES = CS / 64;  // 32
constexpr int ATTN_SMEM = (2 * KBUF + 2 * VBUF + CS) * 4;  // 79872 B
}

// __device__ scratch (no-allocation rule)
__device__ __align__(16) float g_q[CB * CH * CS * CHD];
__device__ __align__(16) float g_k[CB * CH * CS * CHD];
__device__ __align__(16) float g_v[CB * CH * CS * CHD];
__device__ __align__(16) float g_x[CB * CS * CD];   // tf32-rounded X
__device__ __align__(16) float g_wq[CD * CD];       // tf32-rounded weights
__device__ __align__(16) float g_wk[CD * CD];
__device__ __align__(16) float g_wv[CD * CD];

// ---------------------------------------------------------------------------
// helpers
// ---------------------------------------------------------------------------
__device__ __forceinline__ void mma_tf32(float* c, const unsigned* a,
                                         unsigned b0, unsigned b1)
{
    asm volatile(
        "mma.sync.aligned.m16n8k8.row.col.f32.tf32.tf32.f32 "
        "{%0,%1,%2,%3}, {%4,%5,%6,%7}, {%8,%9}, {%0,%1,%2,%3};"
        : "+f"(c[0]), "+f"(c[1]), "+f"(c[2]), "+f"(c[3])
        : "r"(a[0]), "r"(a[1]), "r"(a[2]), "r"(a[3]), "r"(b0), "r"(b1));
}

__device__ __forceinline__ unsigned f2tf32u(float x)
{
    return __float_as_uint(wmma::__float_to_tf32(x));
}

__device__ __forceinline__ void cp16(float* dst_smem, const float* src)
{
    unsigned d = (unsigned)__cvta_generic_to_shared(dst_smem);
    asm volatile("cp.async.cg.shared.global [%0], [%1], 16;" :: "r"(d), "l"(src));
}
__device__ __forceinline__ void cp_commit()
{
    asm volatile("cp.async.commit_group;" ::: "memory");
}
template <int N>
__device__ __forceinline__ void cp_wait()
{
    asm volatile("cp.async.wait_group %0;" :: "n"(N) : "memory");
}

// ---------------------------------------------------------------------------
// Kernel 0: tf32-round X and W into scratch (hoists all in-loop cvt).
// grid = (4096, 4): y selects the array; 4 floats per thread.
// ---------------------------------------------------------------------------
__global__ __launch_bounds__(256)
void round_kernel(const float* __restrict__ X,
                  const float* __restrict__ Wq,
                  const float* __restrict__ Wk,
                  const float* __restrict__ Wv)
{
    const float* src;
    float* dst;
    int n;
    switch (blockIdx.y) {
        case 0:  src = X;  dst = g_x;  n = CB * CS * CD; break;
        case 1:  src = Wq; dst = g_wq; n = CD * CD; break;
        case 2:  src = Wk; dst = g_wk; n = CD * CD; break;
        default: src = Wv; dst = g_wv; n = CD * CD; break;
    }
    int i = (blockIdx.x * 256 + threadIdx.x) * 4;
    if (i < n) {
        float4 v = *reinterpret_cast<const float4*>(src + i);
        v.x = wmma::__float_to_tf32(v.x);
        v.y = wmma::__float_to_tf32(v.y);
        v.z = wmma::__float_to_tf32(v.z);
        v.w = wmma::__float_to_tf32(v.w);
        *reinterpret_cast<float4*>(dst + i) = v;
    }
}

// ---------------------------------------------------------------------------
// Kernel 1: fused QKV projection on raw tf32 mma.
// Block 256x128, 8 warps (4 M x 2 N) of 64x64, K-step 16 double-buffered via
// cp.async. Direct epilogue: bias + tf32-round + head-split scatter, no smem C.
// Fragment layouts (g = lane>>2, t = lane&3):
//   A: a0=(g,t) a1=(g+8,t) a2=(g,t+4) a3=(g+8,t+4)
//   B (k x n, col-maj): b0=(t,g) b1=(t+4,g)
//   C: c0=(g,2t) c1=(g,2t+1) c2=(g+8,2t) c3=(g+8,2t+1)
// ---------------------------------------------------------------------------
__global__ __launch_bounds__(256, 1)
void qkv_kernel(const float* __restrict__ bq, const float* __restrict__ bk,
                const float* __restrict__ bv)
{
    extern __shared__ float sm[];
    float* As = sm;                    // 2 x 256 x QLDA
    float* Bs = sm + 2 * QABUF;        // 2 x 16 x QLDB

    const int z = blockIdx.z;
    const float* W    = (z == 0) ? g_wq : (z == 1) ? g_wk : g_wv;
    const float* bias = (z == 0) ? bq   : (z == 1) ? bk   : bv;
    float* Out        = (z == 0) ? g_q  : (z == 1) ? g_k  : g_v;

    const int m0 = blockIdx.y * 256;
    const int n0 = blockIdx.x * 128;
    const int tid  = threadIdx.x;
    const int warp = tid >> 5;
    const int lane = tid & 31;
    const int g = lane >> 2, t = lane & 3;
    const int wm = warp >> 1;          // 0..3 -> 64-row strip
    const int wn = warp & 1;           // 0..1 -> 64-col strip

    auto copyAB = [&](int ks, int buf) {
        const float* Xs = g_x + (size_t)m0 * CD + ks * 16;
        float* Ad = As + buf * QABUF;
#pragma unroll
        for (int i = 0; i < 4; i++) {
            int idx = tid + i * 256;           // 0..1023
            int r = idx >> 2, c4 = (idx & 3) * 4;
            cp16(Ad + r * QLDA + c4, Xs + (size_t)r * CD + c4);
        }
        const float* Ws = W + (size_t)ks * 16 * CD + n0;
        float* Bd = Bs + buf * QBBUF;
#pragma unroll
        for (int i = 0; i < 2; i++) {
            int idx = tid + i * 256;           // 0..511
            int r = idx >> 5, c4 = (idx & 31) * 4;
            cp16(Bd + r * QLDB + c4, Ws + (size_t)r * CD + c4);
        }
    };

    float acc[4][8][4];
#pragma unroll
    for (int i = 0; i < 4; i++)
#pragma unroll
        for (int n = 0; n < 8; n++)
#pragma unroll
            for (int e = 0; e < 4; e++) acc[i][n][e] = 0.0f;

    copyAB(0, 0);
    cp_commit();

    for (int ks = 0; ks < CD / 16; ks++) {
        if (ks + 1 < CD / 16) {
            copyAB(ks + 1, (ks + 1) & 1);
            cp_commit();
            cp_wait<1>();
        } else {
            cp_wait<0>();
        }
        __syncthreads();

        const float* Ab = As + (ks & 1) * QABUF;
        const float* Bb = Bs + (ks & 1) * QBBUF;
#pragma unroll
        for (int kk = 0; kk < 16; kk += 8) {
            unsigned bf[8][2], af[4][4];
#pragma unroll
            for (int n = 0; n < 8; n++) {
                bf[n][0] = __float_as_uint(Bb[(kk + t) * QLDB + wn * 64 + n * 8 + g]);
                bf[n][1] = __float_as_uint(Bb[(kk + t + 4) * QLDB + wn * 64 + n * 8 + g]);
            }
#pragma unroll
            for (int i = 0; i < 4; i++) {
                int rb = (wm * 64 + i * 16) * QLDA + kk;
                af[i][0] = __float_as_uint(Ab[rb + g * QLDA + t]);
                af[i][1] = __float_as_uint(Ab[rb + (g + 8) * QLDA + t]);
                af[i][2] = __float_as_uint(Ab[rb + g * QLDA + t + 4]);
                af[i][3] = __float_as_uint(Ab[rb + (g + 8) * QLDA + t + 4]);
            }
#pragma unroll
            for (int i = 0; i < 4; i++)
#pragma unroll
                for (int n = 0; n < 8; n++)
                    mma_tf32(acc[i][n], af[i], bf[n][0], bf[n][1]);
        }
        __syncthreads();
    }

    // Epilogue: bias + tf32 round + scatter to [B,H,S,HD]
#pragma unroll
    for (int i = 0; i < 4; i++) {
        int gr0 = m0 + wm * 64 + i * 16 + g;
#pragma unroll
        for (int n = 0; n < 8; n++) {
            int gc = n0 + wn * 64 + n * 8 + t * 2;
            float2 b2 = *reinterpret_cast<const float2*>(bias + gc);
            int h = gc >> 6, hd = gc & 63;
            {
                int bb = gr0 >> 11, s = gr0 & (CS - 1);
                float2 v;
                v.x = wmma::__float_to_tf32(acc[i][n][0] + b2.x);
                v.y = wmma::__float_to_tf32(acc[i][n][1] + b2.y);
                *reinterpret_cast<float2*>(Out + ((size_t)((bb * CH + h) * CS + s)) * CHD + hd) = v;
            }
            {
                int gr1 = gr0 + 8;
                int bb = gr1 >> 11, s = gr1 & (CS - 1);
                float2 v;
                v.x = wmma::__float_to_tf32(acc[i][n][2] + b2.x);
                v.y = wmma::__float_to_tf32(acc[i][n][3] + b2.y);
                *reinterpret_cast<float2*>(Out + ((size_t)((bb * CH + h) * CS + s)) * CHD + hd) = v;
            }
        }
    }
}

// ---------------------------------------------------------------------------
// Kernel 2: register-resident flash attention, 32 q-rows per warp.
// Block = 128 q rows (4 warps); K/V cp.async double-buffered; mask in smem;
// each B fragment (K or V) feeds 2 mmas -> smem bytes/mma halved vs R5-R7.
// ---------------------------------------------------------------------------
__global__ __launch_bounds__(128, 2)
void attn_kernel(const float* __restrict__ mask, float* __restrict__ out)
{
    extern __shared__ float sm[];
    float* Ks  = sm;                           // 2 x KBUF
    float* Vs  = sm + 2 * KBUF;                // 2 x VBUF
    float* msk = sm + 2 * KBUF + 2 * VBUF;     // CS floats

    const int q0 = blockIdx.x * 128;
    const int h  = blockIdx.y;
    const int b  = blockIdx.z;
    const int tid  = threadIdx.x;
    const int warp = tid >> 5;
    const int lane = tid & 31;
    const int g = lane >> 2, t = lane & 3;

    const float* Qg = g_q + ((size_t)((b * CH + h) * CS) + q0 + warp * 32) * CHD;
    const float* Kg = g_k + (size_t)((b * CH + h) * CS) * CHD;
    const float* Vg = g_v + (size_t)((b * CH + h) * CS) * CHD;

    auto copyKV = [&](int j, int buf) {
        const float* Ksrc = Kg + (size_t)j * 64 * CHD;
        const float* Vsrc = Vg + (size_t)j * 64 * CHD;
        float* Kd = Ks + buf * KBUF;
        float* Vd = Vs + buf * VBUF;
#pragma unroll
        for (int i = 0; i < 8; i++) {
            int idx = tid + i * 128;           // 0..1023
            int r = idx >> 4, c4 = (idx & 15) * 4;
            cp16(Kd + r * LDK + c4, Ksrc + r * CHD + c4);
            cp16(Vd + r * LDV + c4, Vsrc + r * CHD + c4);
        }
    };

    // Group 0: first KV tile + full mask row
    copyKV(0, 0);
    {
        const float* mg = mask + b * CS;
#pragma unroll
        for (int i = 0; i < 4; i++) {
            int idx = (tid + i * 128) * 4;
            cp16(msk + idx, mg + idx);
        }
    }
    cp_commit();

    // Q fragments: persistent, pre-scaled by 1/sqrt(64) (exact pow2 on tf32)
    unsigned qf[8][2][4];
#pragma unroll
    for (int kk = 0; kk < 8; kk++)
#pragma unroll
        for (int f = 0; f < 2; f++) {
            int r0 = f * 16 + g;
            qf[kk][f][0] = f2tf32u(Qg[r0 * CHD + kk * 8 + t] * 0.125f);
            qf[kk][f][1] = f2tf32u(Qg[(r0 + 8) * CHD + kk * 8 + t] * 0.125f);
            qf[kk][f][2] = f2tf32u(Qg[r0 * CHD + kk * 8 + t + 4] * 0.125f);
            qf[kk][f][3] = f2tf32u(Qg[(r0 + 8) * CHD + kk * 8 + t + 4] * 0.125f);
        }

    float oacc[2][8][4];
#pragma unroll
    for (int f = 0; f < 2; f++)
#pragma unroll
        for (int n = 0; n < 8; n++)
#pragma unroll
            for (int e = 0; e < 4; e++) oacc[f][n][e] = 0.0f;

    float mrun[2][2] = {{-1e30f, -1e30f}, {-1e30f, -1e30f}};
    float lrun[2][2] = {{0.0f, 0.0f}, {0.0f, 0.0f}};

    for (int j = 0; j < NTILES; j++) {
        if (j + 1 < NTILES) {
            copyKV(j + 1, (j + 1) & 1);
            cp_commit();
            cp_wait<1>();
        } else {
            cp_wait<0>();
        }
        __syncthreads();

        const float* Kb = Ks + (j & 1) * KBUF;
        const float* Vb = Vs + (j & 1) * VBUF;

        // ---- S = (Q/8) @ K^T ----
        float s[2][8][4];
#pragma unroll
        for (int f = 0; f < 2; f++)
#pragma unroll
            for (int n = 0; n < 8; n++)
#pragma unroll
                for (int e = 0; e < 4; e++) s[f][n][e] = 0.0f;

#pragma unroll
        for (int kk = 0; kk < 8; kk++)
#pragma unroll
            for (int n = 0; n < 8; n++) {
                unsigned b0 = __float_as_uint(Kb[(n * 8 + g) * LDK + kk * 8 + t]);
                unsigned b1 = __float_as_uint(Kb[(n * 8 + g) * LDK + kk * 8 + t + 4]);
                mma_tf32(s[0][n], qf[kk][0], b0, b1);
                mma_tf32(s[1][n], qf[kk][1], b0, b1);
            }

        // ---- online softmax (register-resident) ----
        const float* mrow = msk + j * 64;
#pragma unroll
        for (int f = 0; f < 2; f++) {
            float mx0 = -1e30f, mx1 = -1e30f;
#pragma unroll
            for (int n = 0; n < 8; n++) {
                float2 mk = *reinterpret_cast<const float2*>(mrow + n * 8 + t * 2);
                s[f][n][0] += mk.x; s[f][n][1] += mk.y;
                s[f][n][2] += mk.x; s[f][n][3] += mk.y;
                mx0 = fmaxf(mx0, fmaxf(s[f][n][0], s[f][n][1]));
                mx1 = fmaxf(mx1, fmaxf(s[f][n][2], s[f][n][3]));
            }
            mx0 = fmaxf(mx0, __shfl_xor_sync(0xffffffffu, mx0, 1));
            mx0 = fmaxf(mx0, __shfl_xor_sync(0xffffffffu, mx0, 2));
            mx1 = fmaxf(mx1, __shfl_xor_sync(0xffffffffu, mx1, 1));
            mx1 = fmaxf(mx1, __shfl_xor_sync(0xffffffffu, mx1, 2));

            float mn0 = fmaxf(mrun[f][0], mx0), mn1 = fmaxf(mrun[f][1], mx1);
            float c0 = __expf(mrun[f][0] - mn0), c1 = __expf(mrun[f][1] - mn1);
            mrun[f][0] = mn0; mrun[f][1] = mn1;

            float s0 = 0.0f, s1 = 0.0f;
#pragma unroll
            for (int n = 0; n < 8; n++) {
                s[f][n][0] = __expf(s[f][n][0] - mn0); s0 += s[f][n][0];
                s[f][n][1] = __expf(s[f][n][1] - mn0); s0 += s[f][n][1];
                s[f][n][2] = __expf(s[f][n][2] - mn1); s1 += s[f][n][2];
                s[f][n][3] = __expf(s[f][n][3] - mn1); s1 += s[f][n][3];
            }
            s0 += __shfl_xor_sync(0xffffffffu, s0, 1);
            s0 += __shfl_xor_sync(0xffffffffu, s0, 2);
            s1 += __shfl_xor_sync(0xffffffffu, s1, 1);
            s1 += __shfl_xor_sync(0xffffffffu, s1, 2);
            lrun[f][0] = lrun[f][0] * c0 + s0;
            lrun[f][1] = lrun[f][1] * c1 + s1;

#pragma unroll
            for (int n = 0; n < 8; n++) {
                oacc[f][n][0] *= c0; oacc[f][n][1] *= c0;
                oacc[f][n][2] *= c1; oacc[f][n][3] *= c1;
            }
        }

        // ---- O += P @ V ----
        const int srcA = (lane & ~3) | (t >> 1);
        const int srcB = srcA + 2;
        const bool odd = (t & 1);
#pragma unroll
        for (int kk = 0; kk < 8; kk++) {
            unsigned a[2][4];
#pragma unroll
            for (int f = 0; f < 2; f++) {
                float e0 = __shfl_sync(0xffffffffu, s[f][kk][0], srcA);
                float o0 = __shfl_sync(0xffffffffu, s[f][kk][1], srcA);
                float e1 = __shfl_sync(0xffffffffu, s[f][kk][2], srcA);
                float o1 = __shfl_sync(0xffffffffu, s[f][kk][3], srcA);
                float e2 = __shfl_sync(0xffffffffu, s[f][kk][0], srcB);
                float o2 = __shfl_sync(0xffffffffu, s[f][kk][1], srcB);
                float e3 = __shfl_sync(0xffffffffu, s[f][kk][2], srcB);
                float o3 = __shfl_sync(0xffffffffu, s[f][kk][3], srcB);
                a[f][0] = f2tf32u(odd ? o0 : e0);
                a[f][1] = f2tf32u(odd ? o1 : e1);
                a[f][2] = f2tf32u(odd ? o2 : e2);
                a[f][3] = f2tf32u(odd ? o3 : e3);
            }
#pragma unroll
            for (int n = 0; n < 8; n++) {
                unsigned b0 = __float_as_uint(Vb[(kk * 8 + t) * LDV + n * 8 + g]);
                unsigned b1 = __float_as_uint(Vb[(kk * 8 + t + 4) * LDV + n * 8 + g]);
                mma_tf32(oacc[0][n], a[0], b0, b1);
                mma_tf32(oacc[1][n], a[1], b0, b1);
            }
        }
        __syncthreads();
    }

    // ---- epilogue: out[b, s, h*64 + c] = O / l ----
#pragma unroll
    for (int f = 0; f < 2; f++) {
        int rowA = q0 + warp * 32 + f * 16 + g;
        float ra = 1.0f / lrun[f][0], rb = 1.0f / lrun[f][1];
#pragma unroll
        for (int n = 0; n < 8; n++) {
            float2 v0 = make_float2(oacc[f][n][0] * ra, oacc[f][n][1] * ra);
            float2 v1 = make_float2(oacc[f][n][2] * rb, oacc[f][n][3] * rb);
            *reinterpret_cast<float2*>(out + (size_t)(b * CS + rowA) * CD + h * CHD + n * 8 + t * 2) = v0;
            *reinterpret_cast<float2*>(out + (size_t)(b * CS + rowA + 8) * CD + h * CHD + n * 8 + t * 2) = v1;
        }
    }
}

// ---------------------------------------------------------------------------
// kernel_launch
// Inputs (metadata order): hidden_states, attention_mask, Wq, bq, Wk, bk, Wv, bv
// ---------------------------------------------------------------------------
extern "C" void kernel_launch(void* const* d_in, const int* in_sizes, int n_in,
                              void* d_out, int out_size)
{
    (void)in_sizes; (void)n_in; (void)out_size;
    const float* X    = (const float*)d_in[0];
    const float* mask = (const float*)d_in[1];
    const float* Wq   = (const float*)d_in[2];
    const float* bq   = (const float*)d_in[3];
    const float* Wk   = (const float*)d_in[4];
    const float* bk   = (const float*)d_in[5];
    const float* Wv   = (const float*)d_in[6];
    const float* bv   = (const float*)d_in[7];
    float* out = (float*)d_out;

    cudaFuncSetAttribute(qkv_kernel, cudaFuncAttributeMaxDynamicSharedMemorySize,
                         QKV_SMEM);
    cudaFuncSetAttribute(attn_kernel, cudaFuncAttributeMaxDynamicSharedMemorySize,
                         ATTN_SMEM);

    // 0) round X, Wq, Wk, Wv to tf32 once
    round_kernel<<<dim3(4096, 4), 256>>>(X, Wq, Wk, Wv);
    // 1) QKV: grid = (N tiles 1024/128, M tiles 4096/256, {q,k,v})
    qkv_kernel<<<dim3(8, 16, 3), 256, QKV_SMEM>>>(bq, bk, bv);
    // 2) attention: grid = (S/128 query tiles, H, B)
    attn_kernel<<<dim3(CS / 128, CH, CB), 128, ATTN_SMEM>>>(mask, out);
}

// round 17
// speedup vs baseline: 3.0638x; 1.0590x over previous
#include <cuda_runtime.h>
#include <mma.h>

using namespace nvcuda;

// Problem constants: TFRobertaSelfAttention B=2, S=2048, D=1024, H=16, HD=64
namespace {
constexpr int CB = 2;      // batch
constexpr int CS = 2048;   // seq len
constexpr int CD = 1024;   // hidden
constexpr int CH = 16;     // heads
constexpr int CHD = 64;    // head dim

// QKV tiling: block 256(M) x 128(N), K-step 16, 8 warps of 64x64
constexpr int QLDA = 20;     // 16 + 4 pad
constexpr int QLDB = 136;    // 128 + 8 pad
constexpr int QABUF = 256 * QLDA;   // 5120 floats per buffer
constexpr int QBBUF = 16 * QLDB;    // 2176 floats per buffer
constexpr int QKV_SMEM = (2 * QABUF + 2 * QBBUF) * 4;  // 58368 B

// Attention tiling: block = 128 q rows, 4 warps x 32 rows, KV tile 64
// LDK/LDV = 72 (== 8 mod 32): float2 LDS at (row*72 + 2t) hits all 32 banks
// exactly once per half-warp.
constexpr int LDK = 72;
constexpr int LDV = 72;          // V^T tile: rows = hd, cols = s
constexpr int KBUF = 64 * LDK;   // 4608
constexpr int VBUF = 64 * LDV;   // 4608
constexpr int NTILES = CS / 64;  // 32
constexpr int ATTN_SMEM = (2 * KBUF + 2 * VBUF) * 4;  // 73728 B
}

// __device__ scratch (no-allocation rule)
__device__ __align__(16) float g_q[CB * CH * CS * CHD];
__device__ __align__(16) float g_k[CB * CH * CS * CHD];
__device__ __align__(16) float g_v[CB * CH * CS * CHD];
__device__ __align__(16) float g_vt[CB * CH * CS * CHD];  // V transposed [b,h][hd][s]
__device__ __align__(16) float g_x[CB * CS * CD];   // tf32-rounded X
__device__ __align__(16) float g_wq[CD * CD];       // tf32-rounded weights
__device__ __align__(16) float g_wk[CD * CD];
__device__ __align__(16) float g_wv[CD * CD];

// ---------------------------------------------------------------------------
// helpers
// ---------------------------------------------------------------------------
__device__ __forceinline__ void mma_tf32(float* c, const unsigned* a,
                                         unsigned b0, unsigned b1)
{
    asm volatile(
        "mma.sync.aligned.m16n8k8.row.col.f32.tf32.tf32.f32 "
        "{%0,%1,%2,%3}, {%4,%5,%6,%7}, {%8,%9}, {%0,%1,%2,%3};"
        : "+f"(c[0]), "+f"(c[1]), "+f"(c[2]), "+f"(c[3])
        : "r"(a[0]), "r"(a[1]), "r"(a[2]), "r"(a[3]), "r"(b0), "r"(b1));
}

__device__ __forceinline__ unsigned f2tf32u(float x)
{
    return __float_as_uint(wmma::__float_to_tf32(x));
}

__device__ __forceinline__ void cp16(float* dst_smem, const float* src)
{
    unsigned d = (unsigned)__cvta_generic_to_shared(dst_smem);
    asm volatile("cp.async.cg.shared.global [%0], [%1], 16;" :: "r"(d), "l"(src));
}
__device__ __forceinline__ void cp_commit()
{
    asm volatile("cp.async.commit_group;" ::: "memory");
}
template <int N>
__device__ __forceinline__ void cp_wait()
{
    asm volatile("cp.async.wait_group %0;" :: "n"(N) : "memory");
}

// ---------------------------------------------------------------------------
// Kernel 0: tf32-round X and W into scratch (hoists all in-loop cvt).
// ---------------------------------------------------------------------------
__global__ __launch_bounds__(256)
void round_kernel(const float* __restrict__ X,
                  const float* __restrict__ Wq,
                  const float* __restrict__ Wk,
                  const float* __restrict__ Wv)
{
    const float* src;
    float* dst;
    int n;
    switch (blockIdx.y) {
        case 0:  src = X;  dst = g_x;  n = CB * CS * CD; break;
        case 1:  src = Wq; dst = g_wq; n = CD * CD; break;
        case 2:  src = Wk; dst = g_wk; n = CD * CD; break;
        default: src = Wv; dst = g_wv; n = CD * CD; break;
    }
    int i = (blockIdx.x * 256 + threadIdx.x) * 4;
    if (i < n) {
        float4 v = *reinterpret_cast<const float4*>(src + i);
        v.x = wmma::__float_to_tf32(v.x);
        v.y = wmma::__float_to_tf32(v.y);
        v.z = wmma::__float_to_tf32(v.z);
        v.w = wmma::__float_to_tf32(v.w);
        *reinterpret_cast<float4*>(dst + i) = v;
    }
}

// ---------------------------------------------------------------------------
// Kernel 1: fused QKV projection on raw tf32 mma (unchanged, passing at R13).
// ---------------------------------------------------------------------------
__global__ __launch_bounds__(256, 1)
void qkv_kernel(const float* __restrict__ bq, const float* __restrict__ bk,
                const float* __restrict__ bv)
{
    extern __shared__ float sm[];
    float* As = sm;                    // 2 x 256 x QLDA
    float* Bs = sm + 2 * QABUF;        // 2 x 16 x QLDB

    const int z = blockIdx.z;
    const float* W    = (z == 0) ? g_wq : (z == 1) ? g_wk : g_wv;
    const float* bias = (z == 0) ? bq   : (z == 1) ? bk   : bv;
    float* Out        = (z == 0) ? g_q  : (z == 1) ? g_k  : g_v;

    const int m0 = blockIdx.y * 256;
    const int n0 = blockIdx.x * 128;
    const int tid  = threadIdx.x;
    const int warp = tid >> 5;
    const int lane = tid & 31;
    const int g = lane >> 2, t = lane & 3;
    const int wm = warp >> 1;          // 0..3 -> 64-row strip
    const int wn = warp & 1;           // 0..1 -> 64-col strip

    auto copyAB = [&](int ks, int buf) {
        const float* Xs = g_x + (size_t)m0 * CD + ks * 16;
        float* Ad = As + buf * QABUF;
#pragma unroll
        for (int i = 0; i < 4; i++) {
            int idx = tid + i * 256;           // 0..1023
            int r = idx >> 2, c4 = (idx & 3) * 4;
            cp16(Ad + r * QLDA + c4, Xs + (size_t)r * CD + c4);
        }
        const float* Ws = W + (size_t)ks * 16 * CD + n0;
        float* Bd = Bs + buf * QBBUF;
#pragma unroll
        for (int i = 0; i < 2; i++) {
            int idx = tid + i * 256;           // 0..511
            int r = idx >> 5, c4 = (idx & 31) * 4;
            cp16(Bd + r * QLDB + c4, Ws + (size_t)r * CD + c4);
        }
    };

    float acc[4][8][4];
#pragma unroll
    for (int i = 0; i < 4; i++)
#pragma unroll
        for (int n = 0; n < 8; n++)
#pragma unroll
            for (int e = 0; e < 4; e++) acc[i][n][e] = 0.0f;

    copyAB(0, 0);
    cp_commit();

    for (int ks = 0; ks < CD / 16; ks++) {
        if (ks + 1 < CD / 16) {
            copyAB(ks + 1, (ks + 1) & 1);
            cp_commit();
            cp_wait<1>();
        } else {
            cp_wait<0>();
        }
        __syncthreads();

        const float* Ab = As + (ks & 1) * QABUF;
        const float* Bb = Bs + (ks & 1) * QBBUF;
#pragma unroll
        for (int kk = 0; kk < 16; kk += 8) {
            unsigned bf[8][2], af[4][4];
#pragma unroll
            for (int n = 0; n < 8; n++) {
                bf[n][0] = __float_as_uint(Bb[(kk + t) * QLDB + wn * 64 + n * 8 + g]);
                bf[n][1] = __float_as_uint(Bb[(kk + t + 4) * QLDB + wn * 64 + n * 8 + g]);
            }
#pragma unroll
            for (int i = 0; i < 4; i++) {
                int rb = (wm * 64 + i * 16) * QLDA + kk;
                af[i][0] = __float_as_uint(Ab[rb + g * QLDA + t]);
                af[i][1] = __float_as_uint(Ab[rb + (g + 8) * QLDA + t]);
                af[i][2] = __float_as_uint(Ab[rb + g * QLDA + t + 4]);
                af[i][3] = __float_as_uint(Ab[rb + (g + 8) * QLDA + t + 4]);
            }
#pragma unroll
            for (int i = 0; i < 4; i++)
#pragma unroll
                for (int n = 0; n < 8; n++)
                    mma_tf32(acc[i][n], af[i], bf[n][0], bf[n][1]);
        }
        __syncthreads();
    }

    // Epilogue: bias + tf32 round + scatter to [B,H,S,HD]
#pragma unroll
    for (int i = 0; i < 4; i++) {
        int gr0 = m0 + wm * 64 + i * 16 + g;
#pragma unroll
        for (int n = 0; n < 8; n++) {
            int gc = n0 + wn * 64 + n * 8 + t * 2;
            float2 b2 = *reinterpret_cast<const float2*>(bias + gc);
            int h = gc >> 6, hd = gc & 63;
            {
                int bb = gr0 >> 11, s = gr0 & (CS - 1);
                float2 v;
                v.x = wmma::__float_to_tf32(acc[i][n][0] + b2.x);
                v.y = wmma::__float_to_tf32(acc[i][n][1] + b2.y);
                *reinterpret_cast<float2*>(Out + ((size_t)((bb * CH + h) * CS + s)) * CHD + hd) = v;
            }
            {
                int gr1 = gr0 + 8;
                int bb = gr1 >> 11, s = gr1 & (CS - 1);
                float2 v;
                v.x = wmma::__float_to_tf32(acc[i][n][2] + b2.x);
                v.y = wmma::__float_to_tf32(acc[i][n][3] + b2.y);
                *reinterpret_cast<float2*>(Out + ((size_t)((bb * CH + h) * CS + s)) * CHD + hd) = v;
            }
        }
    }
}

// ---------------------------------------------------------------------------
// Kernel 1b: V transpose per (b,h): [s][hd] -> [hd][s].  32x32 smem tiles.
// ---------------------------------------------------------------------------
__global__ __launch_bounds__(256)
void vtrans_kernel()
{
    __shared__ float tile[32][33];
    const int bh = blockIdx.z;
    const int s0 = blockIdx.x * 32;
    const int d0 = blockIdx.y * 32;
    const float* src = g_v  + (size_t)bh * CS * CHD;
    float*       dst = g_vt + (size_t)bh * CS * CHD;
    const int tx = threadIdx.x & 31, ty = threadIdx.x >> 5;  // 32 x 8
#pragma unroll
    for (int i = 0; i < 32; i += 8)
        tile[ty + i][tx] = src[(size_t)(s0 + ty + i) * CHD + d0 + tx];
    __syncthreads();
#pragma unroll
    for (int i = 0; i < 32; i += 8)
        dst[(size_t)(d0 + ty + i) * CS + s0 + tx] = tile[tx][ty + i];
}

// ---------------------------------------------------------------------------
// Kernel 2: register-resident flash attention, 32 q-rows per warp.
//
// k-dim permutation trick: mma.m16n8k8 sums over k; we remap its k-index
// via sigma(t)=2t, sigma(t+4)=2t+1 (a bijection), applied to BOTH operands:
//  - S = Q@K^T (k = head dim): B-fragment reads K cols {2t, 2t+1} -> one
//    conflict-free LDS.64; Q fragments read the permuted cols (registers).
//  - O += P@V (k = kv pos): A-fragment slots map to P accumulator regs
//    {c0, c2, c1, c3} DIRECTLY (no shuffles!), and B-fragment reads V^T
//    cols {2t, 2t+1} -> one conflict-free LDS.64.
// Mask comes straight from L1/L2 via LDG.64 (no smem copy).
// ---------------------------------------------------------------------------
__global__ __launch_bounds__(128, 2)
void attn_kernel(const float* __restrict__ mask, float* __restrict__ out)
{
    extern __shared__ float sm[];
    float* Ks = sm;                // 2 x 64 x LDK   (row = s, col = hd)
    float* Vs = sm + 2 * KBUF;     // 2 x 64 x LDV   (row = hd, col = s)

    const int q0 = blockIdx.x * 128;
    const int h  = blockIdx.y;
    const int b  = blockIdx.z;
    const int tid  = threadIdx.x;
    const int warp = tid >> 5;
    const int lane = tid & 31;
    const int g = lane >> 2, t = lane & 3;

    const float* Qg  = g_q  + ((size_t)((b * CH + h) * CS) + q0 + warp * 32) * CHD;
    const float* Kg  = g_k  + (size_t)((b * CH + h) * CS) * CHD;
    const float* Vtg = g_vt + (size_t)(b * CH + h) * CS * CHD;  // [hd][s]

    auto copyKV = [&](int j, int buf) {
        const float* Ksrc = Kg + (size_t)j * 64 * CHD;
        float* Kd = Ks + buf * KBUF;
        float* Vd = Vs + buf * VBUF;
#pragma unroll
        for (int i = 0; i < 8; i++) {
            int idx = tid + i * 128;           // 0..1023
            int r = idx >> 4, c4 = (idx & 15) * 4;
            cp16(Kd + r * LDK + c4, Ksrc + r * CHD + c4);
            // V^T: row r = hd, cols = s slice of this tile
            cp16(Vd + r * LDV + c4, Vtg + (size_t)r * CS + j * 64 + c4);
        }
    };

    copyKV(0, 0);
    cp_commit();

    // Q fragments: persistent, pre-scaled by 1/sqrt(64); permuted k-cols.
    unsigned qf[8][2][4];
#pragma unroll
    for (int kk = 0; kk < 8; kk++)
#pragma unroll
        for (int f = 0; f < 2; f++) {
            int r0 = f * 16 + g;
            qf[kk][f][0] = f2tf32u(Qg[r0 * CHD + kk * 8 + 2 * t] * 0.125f);
            qf[kk][f][1] = f2tf32u(Qg[(r0 + 8) * CHD + kk * 8 + 2 * t] * 0.125f);
            qf[kk][f][2] = f2tf32u(Qg[r0 * CHD + kk * 8 + 2 * t + 1] * 0.125f);
            qf[kk][f][3] = f2tf32u(Qg[(r0 + 8) * CHD + kk * 8 + 2 * t + 1] * 0.125f);
        }

    float oacc[2][8][4];
#pragma unroll
    for (int f = 0; f < 2; f++)
#pragma unroll
        for (int n = 0; n < 8; n++)
#pragma unroll
            for (int e = 0; e < 4; e++) oacc[f][n][e] = 0.0f;

    float mrun[2][2] = {{-1e30f, -1e30f}, {-1e30f, -1e30f}};
    float lrun[2][2] = {{0.0f, 0.0f}, {0.0f, 0.0f}};

    for (int j = 0; j < NTILES; j++) {
        if (j + 1 < NTILES) {
            copyKV(j + 1, (j + 1) & 1);
            cp_commit();
            cp_wait<1>();
        } else {
            cp_wait<0>();
        }
        __syncthreads();

        const float* Kb = Ks + (j & 1) * KBUF;
        const float* Vb = Vs + (j & 1) * VBUF;

        // ---- S = (Q/8) @ K^T : one LDS.64 per (kk,n), feeds 2 mmas ----
        float s[2][8][4];
#pragma unroll
        for (int f = 0; f < 2; f++)
#pragma unroll
            for (int n = 0; n < 8; n++)
#pragma unroll
                for (int e = 0; e < 4; e++) s[f][n][e] = 0.0f;

#pragma unroll
        for (int kk = 0; kk < 8; kk++)
#pragma unroll
            for (int n = 0; n < 8; n++) {
                float2 kb = *reinterpret_cast<const float2*>(
                    Kb + (n * 8 + g) * LDK + kk * 8 + 2 * t);
                unsigned b0 = __float_as_uint(kb.x);
                unsigned b1 = __float_as_uint(kb.y);
                mma_tf32(s[0][n], qf[kk][0], b0, b1);
                mma_tf32(s[1][n], qf[kk][1], b0, b1);
            }

        // ---- mask (cached LDG) + online softmax (register-resident) ----
        const float* mrow = mask + b * CS + j * 64;
        float2 mk[8];
#pragma unroll
        for (int n = 0; n < 8; n++)
            mk[n] = *reinterpret_cast<const float2*>(mrow + n * 8 + t * 2);

#pragma unroll
        for (int f = 0; f < 2; f++) {
            float mx0 = -1e30f, mx1 = -1e30f;
#pragma unroll
            for (int n = 0; n < 8; n++) {
                s[f][n][0] += mk[n].x; s[f][n][1] += mk[n].y;
                s[f][n][2] += mk[n].x; s[f][n][3] += mk[n].y;
                mx0 = fmaxf(mx0, fmaxf(s[f][n][0], s[f][n][1]));
                mx1 = fmaxf(mx1, fmaxf(s[f][n][2], s[f][n][3]));
            }
            mx0 = fmaxf(mx0, __shfl_xor_sync(0xffffffffu, mx0, 1));
            mx0 = fmaxf(mx0, __shfl_xor_sync(0xffffffffu, mx0, 2));
            mx1 = fmaxf(mx1, __shfl_xor_sync(0xffffffffu, mx1, 1));
            mx1 = fmaxf(mx1, __shfl_xor_sync(0xffffffffu, mx1, 2));

            float mn0 = fmaxf(mrun[f][0], mx0), mn1 = fmaxf(mrun[f][1], mx1);
            float c0 = __expf(mrun[f][0] - mn0), c1 = __expf(mrun[f][1] - mn1);
            mrun[f][0] = mn0; mrun[f][1] = mn1;

            float s0 = 0.0f, s1 = 0.0f;
#pragma unroll
            for (int n = 0; n < 8; n++) {
                s[f][n][0] = __expf(s[f][n][0] - mn0); s0 += s[f][n][0];
                s[f][n][1] = __expf(s[f][n][1] - mn0); s0 += s[f][n][1];
                s[f][n][2] = __expf(s[f][n][2] - mn1); s1 += s[f][n][2];
                s[f][n][3] = __expf(s[f][n][3] - mn1); s1 += s[f][n][3];
            }
            s0 += __shfl_xor_sync(0xffffffffu, s0, 1);
            s0 += __shfl_xor_sync(0xffffffffu, s0, 2);
            s1 += __shfl_xor_sync(0xffffffffu, s1, 1);
            s1 += __shfl_xor_sync(0xffffffffu, s1, 2);
            lrun[f][0] = lrun[f][0] * c0 + s0;
            lrun[f][1] = lrun[f][1] * c1 + s1;

#pragma unroll
            for (int n = 0; n < 8; n++) {
                oacc[f][n][0] *= c0; oacc[f][n][1] *= c0;
                oacc[f][n][2] *= c1; oacc[f][n][3] *= c1;
            }
        }

        // ---- O += P @ V : A-frag = {c0,c2,c1,c3} (no shuffles), V^T LDS.64 ----
#pragma unroll
        for (int kk = 0; kk < 8; kk++) {
            unsigned a0[4] = { f2tf32u(s[0][kk][0]), f2tf32u(s[0][kk][2]),
                               f2tf32u(s[0][kk][1]), f2tf32u(s[0][kk][3]) };
            unsigned a1[4] = { f2tf32u(s[1][kk][0]), f2tf32u(s[1][kk][2]),
                               f2tf32u(s[1][kk][1]), f2tf32u(s[1][kk][3]) };
#pragma unroll
            for (int n = 0; n < 8; n++) {
                float2 vb = *reinterpret_cast<const float2*>(
                    Vb + (n * 8 + g) * LDV + kk * 8 + 2 * t);
                unsigned b0 = __float_as_uint(vb.x);
                unsigned b1 = __float_as_uint(vb.y);
                mma_tf32(oacc[0][n], a0, b0, b1);
                mma_tf32(oacc[1][n], a1, b0, b1);
            }
        }
        __syncthreads();
    }

    // ---- epilogue: out[b, s, h*64 + c] = O / l ----
#pragma unroll
    for (int f = 0; f < 2; f++) {
        int rowA = q0 + warp * 32 + f * 16 + g;
        float ra = 1.0f / lrun[f][0], rb = 1.0f / lrun[f][1];
#pragma unroll
        for (int n = 0; n < 8; n++) {
            float2 v0 = make_float2(oacc[f][n][0] * ra, oacc[f][n][1] * ra);
            float2 v1 = make_float2(oacc[f][n][2] * rb, oacc[f][n][3] * rb);
            *reinterpret_cast<float2*>(out + (size_t)(b * CS + rowA) * CD + h * CHD + n * 8 + t * 2) = v0;
            *reinterpret_cast<float2*>(out + (size_t)(b * CS + rowA + 8) * CD + h * CHD + n * 8 + t * 2) = v1;
        }
    }
}

// ---------------------------------------------------------------------------
// kernel_launch
// Inputs (metadata order): hidden_states, attention_mask, Wq, bq, Wk, bk, Wv, bv
// ---------------------------------------------------------------------------
extern "C" void kernel_launch(void* const* d_in, const int* in_sizes, int n_in,
                              void* d_out, int out_size)
{
    (void)in_sizes; (void)n_in; (void)out_size;
    const float* X    = (const float*)d_in[0];
    const float* mask = (const float*)d_in[1];
    const float* Wq   = (const float*)d_in[2];
    const float* bq   = (const float*)d_in[3];
    const float* Wk   = (const float*)d_in[4];
    const float* bk   = (const float*)d_in[5];
    const float* Wv   = (const float*)d_in[6];
    const float* bv   = (const float*)d_in[7];
    float* out = (float*)d_out;

    cudaFuncSetAttribute(qkv_kernel, cudaFuncAttributeMaxDynamicSharedMemorySize,
                         QKV_SMEM);
    cudaFuncSetAttribute(attn_kernel, cudaFuncAttributeMaxDynamicSharedMemorySize,
                         ATTN_SMEM);

    // 0) round X, Wq, Wk, Wv to tf32 once
    round_kernel<<<dim3(4096, 4), 256>>>(X, Wq, Wk, Wv);
    // 1) QKV: grid = (N tiles 1024/128, M tiles 4096/256, {q,k,v})
    qkv_kernel<<<dim3(8, 16, 3), 256, QKV_SMEM>>>(bq, bk, bv);
    // 1b) transpose V per (b,h): [s][hd] -> [hd][s]
    vtrans_kernel<<<dim3(CS / 32, CHD / 32, CB * CH), 256>>>();
    // 2) attention: grid = (S/128 query tiles, H, B)
    attn_kernel<<<dim3(CS / 128, CH, CB), 128, ATTN_SMEM>>>(mask, out);
}